// round 15
// baseline (speedup 1.0000x reference)
#include <cuda_runtime.h>
#include <cstdint>

typedef uint32_t u32;

#define TN   128
#define NTH  128

// ---------- global fp16-split weight images (written by prep kernel) ----------
__device__ __align__(16) u32 g_UWS[16896];
__device__ __align__(16) u32 g_GS[40960];
__device__ __align__(16) u32 g_UOS[10240];

// ---------- smem byte offsets ----------
#define OFF_P0   0            // fp32 [128][36] = 18432
#define OFF_SCR  18432        // 40960-byte scratch region
#define OFF_UW   OFF_SCR      // per-d Uw hi image 16896
#define OFF_G    OFF_SCR      // G hi pingpong 2 x 20480 = 40960
#define OFF_UO   OFF_SCR      // Uo hi at +0, Uo lo at +20480
#define OFF_UB   59392        // 256 B bias
#define SMEM_TOTAL 59648      // x3 CTAs = 178944

__device__ __forceinline__ u32 s2u(const void* p) {
    u32 a; asm("{.reg .u64 t; cvta.to.shared.u64 t,%1; cvt.u32.u64 %0,t;}" : "=r"(a) : "l"(p));
    return a;
}
__device__ __forceinline__ void cpa16(u32 dst, const void* src) {
    asm volatile("cp.async.ca.shared.global [%0],[%1],16;" :: "r"(dst), "l"(src));
}
#define CPA_COMMIT asm volatile("cp.async.commit_group;" ::: "memory")
#define CPA_WAIT0  asm volatile("cp.async.wait_group 0;" ::: "memory")

__device__ __forceinline__ void ldmx4(u32& r0, u32& r1, u32& r2, u32& r3, u32 addr) {
    asm volatile("ldmatrix.sync.aligned.m8n8.x4.shared.b16 {%0,%1,%2,%3},[%4];"
                 : "=r"(r0), "=r"(r1), "=r"(r2), "=r"(r3) : "r"(addr));
}

__device__ __forceinline__ u32 pkh(float flo, float fhi) {
    u32 r; asm("cvt.rn.f16x2.f32 %0,%1,%2;" : "=r"(r) : "f"(fhi), "f"(flo)); return r;
}
__device__ __forceinline__ void uph(u32 p, float& flo, float& fhi) {
    asm("{.reg .f16 a,b; mov.b32 {a,b},%2; cvt.f32.f16 %0,a; cvt.f32.f16 %1,b;}"
        : "=f"(flo), "=f"(fhi) : "r"(p));
}
__device__ __forceinline__ void split2h(float x, float y, u32& hi, u32& lo) {
    hi = pkh(x, y);
    float hx, hy; uph(hi, hx, hy);
    lo = pkh(x - hx, y - hy);
}
__device__ __forceinline__ void mma16816(float4& d, u32 a0, u32 a1, u32 a2, u32 a3,
                                         u32 b0, u32 b1) {
    asm("mma.sync.aligned.m16n8k16.row.col.f32.f16.f16.f32 "
        "{%0,%1,%2,%3},{%4,%5,%6,%7},{%8,%9},{%0,%1,%2,%3};"
        : "+f"(d.x), "+f"(d.y), "+f"(d.z), "+f"(d.w)
        : "r"(a0), "r"(a1), "r"(a2), "r"(a3), "r"(b0), "r"(b1));
}

// ================= prep: split weights to fp16 hi/lo global images =================
__global__ void prep_kernel(const float* __restrict__ Uw,
                            const float* __restrict__ Gg,
                            const float* __restrict__ Uo)
{
    for (int task = blockIdx.x * blockDim.x + threadIdx.x; task < 28672;
         task += gridDim.x * blockDim.x) {
        if (task < 8192) {
            int d = task >> 12, r = (task >> 7) & 31, ip = task & 127;
            float x0 = Uw[d * 8192 + r * 256 + 2 * ip];
            float x1 = Uw[d * 8192 + r * 256 + 2 * ip + 1];
            u32 hi, lo; split2h(x0, x1, hi, lo);
            g_UWS[((d * 2 + 0) * 32 + r) * 132 + ip] = hi;
            g_UWS[((d * 2 + 1) * 32 + r) * 132 + ip] = lo;
        } else if (task < 24576) {
            int t = task - 8192;
            int a = t >> 9, c = (t >> 4) & 31, bp = t & 15;
            float x0 = Gg[a * 1024 + (2 * bp) * 32 + c];
            float x1 = Gg[a * 1024 + (2 * bp + 1) * 32 + c];
            u32 hi, lo; split2h(x0, x1, hi, lo);
            g_GS[((0 * 32 + a) * 32 + c) * 20 + bp] = hi;
            g_GS[((1 * 32 + a) * 32 + c) * 20 + bp] = lo;
        } else {
            int t = task - 24576;
            int o = t >> 4, cp = t & 15;
            float x0 = Uo[o * 32 + 2 * cp];
            float x1 = Uo[o * 32 + 2 * cp + 1];
            u32 hi, lo; split2h(x0, x1, hi, lo);
            g_UOS[(0 * 256 + o) * 20 + cp] = hi;
            g_UOS[(1 * 256 + o) * 20 + cp] = lo;
        }
    }
}

// ================= main: 4 warps, m32 per warp =================
__global__ __launch_bounds__(NTH, 3)
void hosvd_mma(const float* __restrict__ X,
               const float* __restrict__ Ub,
               float* __restrict__ out,
               int nN)
{
    extern __shared__ __align__(16) char sm[];
    const u32 sb   = s2u(sm);
    const int tid  = threadIdx.x;
    const int lane = tid & 31;
    const int q    = lane & 3;
    const int cg   = lane >> 2;
    const int rw   = (tid >> 5) * 32;
    const int base = blockIdx.x * TN;

    // ---- L2 prefetch of this CTA's entire X tile (non-blocking) ----
    {
        int rows = nN - base;
        if (rows > TN) rows = TN;
        if (rows > 0) {
            int nlines = rows * 16;                // 16 x 128B lines per row (2KB)
            const char* xp = (const char*)(X + (size_t)base * 512);
            for (int i = tid; i < nlines; i += NTH)
                asm volatile("prefetch.global.L2 [%0];" :: "l"(xp + (size_t)i * 128));
        }
    }

    const int lm8 = lane & 7, lmm = lane >> 3;
    const u32 lmW  = (u32)(lm8 * 528 + lmm * 16);
    const u32 lm40 = (u32)(lm8 * 80 + lmm * 16);

    int  rA[2], rB[2];
    bool okA[2], okB[2];
    #pragma unroll
    for (int rb = 0; rb < 2; rb++) {
        rA[rb] = rw + rb * 16 + cg;
        rB[rb] = rA[rb] + 8;
        okA[rb] = (base + rA[rb]) < nN;
        okB[rb] = (base + rB[rb]) < nN;
    }

    if (tid < 64) *(float*)(sm + OFF_UB + tid * 4) = Ub[tid];

    u32 pH[2][2][4], pL[2][2][4];

    // ================= Phase 1: P = [Xh @ UwHi_d^T] =================
    for (int d = 0; d < 2; d++) {
        if (d) __syncthreads();
        for (int i = tid; i < 1056; i += NTH)
            cpa16(sb + OFF_UW + i * 16,
                  (const char*)g_UWS + (size_t)d * 33792 + (size_t)i * 16);
        CPA_COMMIT;

        float4 acc[2][4];
        #pragma unroll
        for (int rb = 0; rb < 2; rb++)
            #pragma unroll
            for (int nt = 0; nt < 4; nt++) acc[rb][nt] = make_float4(0.f, 0.f, 0.f, 0.f);

        const float* xb = X + (size_t)base * 512 + d * 256;

        for (int ch = 0; ch < 4; ch++) {
            const int c4 = ch * 64;
            #pragma unroll
            for (int ksh = 0; ksh < 2; ksh++) {
                u32 xh[2][2][4];
                #pragma unroll
                for (int rb = 0; rb < 2; rb++)
                    #pragma unroll
                    for (int ks2 = 0; ks2 < 2; ks2++) {
                        const int kk = c4 + ksh * 32 + ks2 * 16 + q * 2;
                        float2 v00 = okA[rb] ? *(const float2*)(xb + (size_t)rA[rb] * 512 + kk)
                                             : make_float2(0.f, 0.f);
                        float2 v10 = okB[rb] ? *(const float2*)(xb + (size_t)rB[rb] * 512 + kk)
                                             : make_float2(0.f, 0.f);
                        float2 v01 = okA[rb] ? *(const float2*)(xb + (size_t)rA[rb] * 512 + kk + 8)
                                             : make_float2(0.f, 0.f);
                        float2 v11 = okB[rb] ? *(const float2*)(xb + (size_t)rB[rb] * 512 + kk + 8)
                                             : make_float2(0.f, 0.f);
                        xh[rb][ks2][0] = pkh(v00.x, v00.y);
                        xh[rb][ks2][1] = pkh(v10.x, v10.y);
                        xh[rb][ks2][2] = pkh(v01.x, v01.y);
                        xh[rb][ks2][3] = pkh(v11.x, v11.y);
                    }
                if (ch == 0 && ksh == 0) { CPA_WAIT0; __syncthreads(); }

                const u32 wb = sb + OFF_UW + lmW + (u32)((c4 + ksh * 32) * 2);
                u32 bh[4][4];
                #pragma unroll
                for (int nt = 0; nt < 4; nt++)
                    ldmx4(bh[nt][0], bh[nt][1], bh[nt][2], bh[nt][3], wb + (u32)(nt * 4224));
                #pragma unroll
                for (int nt = 0; nt < 4; nt++)
                    #pragma unroll
                    for (int rb = 0; rb < 2; rb++)
                        #pragma unroll
                        for (int ks2 = 0; ks2 < 2; ks2++)
                            mma16816(acc[rb][nt],
                                     xh[rb][ks2][0], xh[rb][ks2][1], xh[rb][ks2][2], xh[rb][ks2][3],
                                     bh[nt][ks2 * 2], bh[nt][ks2 * 2 + 1]);
            }
        }

        float* P0f = (float*)(sm + OFF_P0);
        #pragma unroll
        for (int rb = 0; rb < 2; rb++)
            #pragma unroll
            for (int nt = 0; nt < 4; nt++) {
                int c0 = nt * 8 + q * 2;
                float bx = *(float*)(sm + OFF_UB + (d * 32 + c0) * 4);
                float by = *(float*)(sm + OFF_UB + (d * 32 + c0 + 1) * 4);
                float px0 = acc[rb][nt].x + bx, py0 = acc[rb][nt].y + by;
                float px1 = acc[rb][nt].z + bx, py1 = acc[rb][nt].w + by;
                if (d == 0) {
                    P0f[rA[rb] * 36 + c0] = px0;  P0f[rA[rb] * 36 + c0 + 1] = py0;
                    P0f[rB[rb] * 36 + c0] = px1;  P0f[rB[rb] * 36 + c0 + 1] = py1;
                } else {
                    int ks = nt >> 1, f0 = (nt & 1) * 2;
                    split2h(px0, py0, pH[rb][ks][f0],     pL[rb][ks][f0]);
                    split2h(px1, py1, pH[rb][ks][f0 + 1], pL[rb][ks][f0 + 1]);
                }
            }
    }
    __syncthreads();

    // ================= Phase 2 =================
    float4 acc2[2][4];
    #pragma unroll
    for (int rb = 0; rb < 2; rb++)
        #pragma unroll
        for (int nt = 0; nt < 4; nt++) acc2[rb][nt] = make_float4(0.f, 0.f, 0.f, 0.f);
    {
        const float* P0f = (const float*)(sm + OFF_P0);

        #pragma unroll 1
        for (int i = tid; i < 1280; i += NTH)
            cpa16(sb + OFF_G + i * 16, g_GS + (size_t)i * 4);
        CPA_COMMIT;

        for (int cc = 0; cc < 4; cc++) {
            float4 svA[2][2], svB[2][2];
            #pragma unroll
            for (int rb = 0; rb < 2; rb++) {
                svA[rb][0] = *(const float4*)(P0f + rA[rb] * 36 + cc * 8);
                svA[rb][1] = *(const float4*)(P0f + rA[rb] * 36 + cc * 8 + 4);
                svB[rb][0] = *(const float4*)(P0f + rB[rb] * 36 + cc * 8);
                svB[rb][1] = *(const float4*)(P0f + rB[rb] * 36 + cc * 8 + 4);
            }
            CPA_WAIT0;
            __syncthreads();
            if (cc < 3) {
                int pp = (cc + 1) & 1;
                #pragma unroll 1
                for (int i = tid; i < 1280; i += NTH)
                    cpa16(sb + OFF_G + pp * 20480 + i * 16,
                          g_GS + (size_t)(cc + 1) * 5120 + (size_t)i * 4);
                CPA_COMMIT;
            } else {
                #pragma unroll 1
                for (int i = tid; i < 1280; i += NTH)
                    cpa16(sb + OFF_UO + i * 16, g_UOS + (size_t)i * 4);
                CPA_COMMIT;
            }
            const u32 gb = sb + OFF_G + (u32)((cc & 1) * 20480) + lm40;
            #pragma unroll
            for (int al = 0; al < 8; al++) {
                float s0[2], s1[2];
                #pragma unroll
                for (int rb = 0; rb < 2; rb++) {
                    s0[rb] = ((const float*)&svA[rb][al >> 2])[al & 3];
                    s1[rb] = ((const float*)&svB[rb][al >> 2])[al & 3];
                }
                u32 gh[4][4];
                #pragma unroll
                for (int nt = 0; nt < 4; nt++)
                    ldmx4(gh[nt][0], gh[nt][1], gh[nt][2], gh[nt][3],
                          gb + (u32)(al * 2560 + nt * 640));
                #pragma unroll
                for (int nt = 0; nt < 4; nt++) {
                    #pragma unroll
                    for (int rb = 0; rb < 2; rb++) {
                        float4 t4a = make_float4(0.f, 0.f, 0.f, 0.f);
                        float4 t4b = make_float4(0.f, 0.f, 0.f, 0.f);
                        mma16816(t4a, pH[rb][0][0], pH[rb][0][1], pH[rb][0][2], pH[rb][0][3], gh[nt][0], gh[nt][1]);
                        mma16816(t4b, pL[rb][0][0], pL[rb][0][1], pL[rb][0][2], pL[rb][0][3], gh[nt][0], gh[nt][1]);
                        mma16816(t4a, pH[rb][1][0], pH[rb][1][1], pH[rb][1][2], pH[rb][1][3], gh[nt][2], gh[nt][3]);
                        mma16816(t4b, pL[rb][1][0], pL[rb][1][1], pL[rb][1][2], pL[rb][1][3], gh[nt][2], gh[nt][3]);
                        acc2[rb][nt].x += s0[rb] * (t4a.x + t4b.x);
                        acc2[rb][nt].y += s0[rb] * (t4a.y + t4b.y);
                        acc2[rb][nt].z += s1[rb] * (t4a.z + t4b.z);
                        acc2[rb][nt].w += s1[rb] * (t4a.w + t4b.w);
                    }
                }
            }
        }
    }

    // ---- R epilogue: split directly into rH/rL fragments ----
    u32 rH[2][2][4], rL[2][2][4];
    #pragma unroll
    for (int rb = 0; rb < 2; rb++)
        #pragma unroll
        for (int nt = 0; nt < 4; nt++) {
            int ks = nt >> 1, f0 = (nt & 1) * 2;
            split2h(acc2[rb][nt].x, acc2[rb][nt].y, rH[rb][ks][f0],     rL[rb][ks][f0]);
            split2h(acc2[rb][nt].z, acc2[rb][nt].w, rH[rb][ks][f0 + 1], rL[rb][ks][f0 + 1]);
        }

    __syncthreads();
    #pragma unroll 1
    for (int i = tid; i < 1280; i += NTH)
        cpa16(sb + OFF_UO + 20480 + i * 16, g_UOS + 5120 + (size_t)i * 4);
    CPA_COMMIT;
    CPA_WAIT0;
    __syncthreads();

    // ================= Phase 3: Out = (Rhi+Rlo) @ (UoHi+UoLo)^T =================
    const u32 ub3 = sb + OFF_UO + lm40;
    #pragma unroll 2
    for (int np = 0; np < 16; np++) {
        u32 uh[2][4], ul[2][4];
        #pragma unroll
        for (int j = 0; j < 2; j++) {
            u32 ua = ub3 + (u32)((np * 2 + j) * 640);
            ldmx4(uh[j][0], uh[j][1], uh[j][2], uh[j][3], ua);
            ldmx4(ul[j][0], ul[j][1], ul[j][2], ul[j][3], ua + 20480);
        }
        #pragma unroll
        for (int j = 0; j < 2; j++) {
            const int o0 = (np * 2 + j) * 8 + q * 2;
            #pragma unroll
            for (int rb = 0; rb < 2; rb++) {
                float4 ta = make_float4(0.f, 0.f, 0.f, 0.f);
                float4 tb = make_float4(0.f, 0.f, 0.f, 0.f);
                mma16816(ta, rH[rb][0][0], rH[rb][0][1], rH[rb][0][2], rH[rb][0][3], uh[j][0], uh[j][1]);
                mma16816(tb, rL[rb][0][0], rL[rb][0][1], rL[rb][0][2], rL[rb][0][3], uh[j][0], uh[j][1]);
                mma16816(ta, rH[rb][1][0], rH[rb][1][1], rH[rb][1][2], rH[rb][1][3], uh[j][2], uh[j][3]);
                mma16816(tb, rL[rb][1][0], rL[rb][1][1], rL[rb][1][2], rL[rb][1][3], uh[j][2], uh[j][3]);
                mma16816(ta, rH[rb][0][0], rH[rb][0][1], rH[rb][0][2], rH[rb][0][3], ul[j][0], ul[j][1]);
                mma16816(ta, rH[rb][1][0], rH[rb][1][1], rH[rb][1][2], rH[rb][1][3], ul[j][2], ul[j][3]);
                if (okA[rb])
                    *(float2*)(out + (size_t)(base + rA[rb]) * 256 + o0)
                        = make_float2(ta.x + tb.x, ta.y + tb.y);
                if (okB[rb])
                    *(float2*)(out + (size_t)(base + rB[rb]) * 256 + o0)
                        = make_float2(ta.z + tb.z, ta.w + tb.w);
            }
        }
    }
}

extern "C" void kernel_launch(void* const* d_in, const int* in_sizes, int n_in,
                              void* d_out, int out_size)
{
    const float* X  = (const float*)d_in[0];
    const float* Gg = (const float*)d_in[1];
    const float* Uw = (const float*)d_in[2];
    const float* Ub = (const float*)d_in[3];
    const float* Uo = (const float*)d_in[4];
    float* outp = (float*)d_out;

    int nNodes = in_sizes[0] / 512;

    prep_kernel<<<32, 256>>>(Uw, Gg, Uo);

    cudaFuncSetAttribute(hosvd_mma,
                         cudaFuncAttributeMaxDynamicSharedMemorySize, SMEM_TOTAL);
    int grid = (nNodes + TN - 1) / TN;
    hosvd_mma<<<grid, NTH, SMEM_TOTAL>>>(X, Ub, outp, nNodes);
}

// round 16
// speedup vs baseline: 1.1157x; 1.1157x over previous
#include <cuda_runtime.h>
#include <cstdint>

typedef uint32_t u32;

#define TN   128
#define NTH  128

// ---------- global fp16-split weight images (written by prep kernel) ----------
__device__ __align__(16) u32 g_UWS[16896];
__device__ __align__(16) u32 g_GS[40960];
__device__ __align__(16) u32 g_UOS[10240];

// ---------- smem byte offsets ----------
#define OFF_P0   0            // fp32 [128][36] = 18432
#define OFF_SCR  18432        // 40960-byte scratch region
#define OFF_UW   OFF_SCR      // both Uw hi images: 2 x 16896 = 33792
#define OFF_G    OFF_SCR      // G hi pingpong 2 x 20480 = 40960
#define OFF_UO   OFF_SCR      // Uo hi at +0, Uo lo at +20480
#define OFF_UB   59392        // 256 B bias
#define SMEM_TOTAL 59648      // x3 CTAs = 178944

__device__ __forceinline__ u32 s2u(const void* p) {
    u32 a; asm("{.reg .u64 t; cvta.to.shared.u64 t,%1; cvt.u32.u64 %0,t;}" : "=r"(a) : "l"(p));
    return a;
}
__device__ __forceinline__ void cpa16(u32 dst, const void* src) {
    asm volatile("cp.async.ca.shared.global [%0],[%1],16;" :: "r"(dst), "l"(src));
}
#define CPA_COMMIT asm volatile("cp.async.commit_group;" ::: "memory")
#define CPA_WAIT0  asm volatile("cp.async.wait_group 0;" ::: "memory")

__device__ __forceinline__ void ldmx4(u32& r0, u32& r1, u32& r2, u32& r3, u32 addr) {
    asm volatile("ldmatrix.sync.aligned.m8n8.x4.shared.b16 {%0,%1,%2,%3},[%4];"
                 : "=r"(r0), "=r"(r1), "=r"(r2), "=r"(r3) : "r"(addr));
}

__device__ __forceinline__ u32 pkh(float flo, float fhi) {
    u32 r; asm("cvt.rn.f16x2.f32 %0,%1,%2;" : "=r"(r) : "f"(fhi), "f"(flo)); return r;
}
__device__ __forceinline__ void uph(u32 p, float& flo, float& fhi) {
    asm("{.reg .f16 a,b; mov.b32 {a,b},%2; cvt.f32.f16 %0,a; cvt.f32.f16 %1,b;}"
        : "=f"(flo), "=f"(fhi) : "r"(p));
}
__device__ __forceinline__ void split2h(float x, float y, u32& hi, u32& lo) {
    hi = pkh(x, y);
    float hx, hy; uph(hi, hx, hy);
    lo = pkh(x - hx, y - hy);
}
__device__ __forceinline__ void mma16816(float4& d, u32 a0, u32 a1, u32 a2, u32 a3,
                                         u32 b0, u32 b1) {
    asm("mma.sync.aligned.m16n8k16.row.col.f32.f16.f16.f32 "
        "{%0,%1,%2,%3},{%4,%5,%6,%7},{%8,%9},{%0,%1,%2,%3};"
        : "+f"(d.x), "+f"(d.y), "+f"(d.z), "+f"(d.w)
        : "r"(a0), "r"(a1), "r"(a2), "r"(a3), "r"(b0), "r"(b1));
}

// ================= prep: split weights to fp16 hi/lo global images =================
__global__ void prep_kernel(const float* __restrict__ Uw,
                            const float* __restrict__ Gg,
                            const float* __restrict__ Uo)
{
    for (int task = blockIdx.x * blockDim.x + threadIdx.x; task < 28672;
         task += gridDim.x * blockDim.x) {
        if (task < 8192) {
            int d = task >> 12, r = (task >> 7) & 31, ip = task & 127;
            float x0 = Uw[d * 8192 + r * 256 + 2 * ip];
            float x1 = Uw[d * 8192 + r * 256 + 2 * ip + 1];
            u32 hi, lo; split2h(x0, x1, hi, lo);
            g_UWS[((d * 2 + 0) * 32 + r) * 132 + ip] = hi;
            g_UWS[((d * 2 + 1) * 32 + r) * 132 + ip] = lo;
        } else if (task < 24576) {
            int t = task - 8192;
            int a = t >> 9, c = (t >> 4) & 31, bp = t & 15;
            float x0 = Gg[a * 1024 + (2 * bp) * 32 + c];
            float x1 = Gg[a * 1024 + (2 * bp + 1) * 32 + c];
            u32 hi, lo; split2h(x0, x1, hi, lo);
            g_GS[((0 * 32 + a) * 32 + c) * 20 + bp] = hi;
            g_GS[((1 * 32 + a) * 32 + c) * 20 + bp] = lo;
        } else {
            int t = task - 24576;
            int o = t >> 4, cp = t & 15;
            float x0 = Uo[o * 32 + 2 * cp];
            float x1 = Uo[o * 32 + 2 * cp + 1];
            u32 hi, lo; split2h(x0, x1, hi, lo);
            g_UOS[(0 * 256 + o) * 20 + cp] = hi;
            g_UOS[(1 * 256 + o) * 20 + cp] = lo;
        }
    }
}

// ================= main: 4 warps, m32 per warp =================
__global__ __launch_bounds__(NTH, 3)
void hosvd_mma(const float* __restrict__ X,
               const float* __restrict__ Ub,
               float* __restrict__ out,
               int nN)
{
    extern __shared__ __align__(16) char sm[];
    const u32 sb   = s2u(sm);
    const int tid  = threadIdx.x;
    const int lane = tid & 31;
    const int q    = lane & 3;
    const int cg   = lane >> 2;
    const int rw   = (tid >> 5) * 32;
    const int base = blockIdx.x * TN;

    const int lm8 = lane & 7, lmm = lane >> 3;
    const u32 lmW  = (u32)(lm8 * 528 + lmm * 16);
    const u32 lm40 = (u32)(lm8 * 80 + lmm * 16);

    int  rA[2], rB[2];
    bool okA[2], okB[2];
    #pragma unroll
    for (int rb = 0; rb < 2; rb++) {
        rA[rb] = rw + rb * 16 + cg;
        rB[rb] = rA[rb] + 8;
        okA[rb] = (base + rA[rb]) < nN;
        okB[rb] = (base + rB[rb]) < nN;
    }

    if (tid < 64) *(float*)(sm + OFF_UB + tid * 4) = Ub[tid];

    u32 pH[2][2][4], pL[2][2][4];

    // ================= Phase 1 (merged d): P = [Xh @ UwHi^T], both d at once =================
    {
        // stage BOTH Uw hi images (d=0 at +0, d=1 at +16896)
        for (int i = tid; i < 1056; i += NTH) {
            cpa16(sb + OFF_UW + i * 16, (const char*)g_UWS + (size_t)i * 16);
            cpa16(sb + OFF_UW + 16896 + i * 16,
                  (const char*)g_UWS + 33792 + (size_t)i * 16);
        }
        CPA_COMMIT;

        float4 acc[2][2][4];                  // [d][rb][nt]
        #pragma unroll
        for (int d = 0; d < 2; d++)
            #pragma unroll
            for (int rb = 0; rb < 2; rb++)
                #pragma unroll
                for (int nt = 0; nt < 4; nt++) acc[d][rb][nt] = make_float4(0.f, 0.f, 0.f, 0.f);

        const float* xb0 = X + (size_t)base * 512;

        for (int ch = 0; ch < 4; ch++) {
            const int c4 = ch * 64;
            #pragma unroll
            for (int ksh = 0; ksh < 2; ksh++) {
                // load X fragments for BOTH d: 16 concurrent LDG.64
                u32 xh[2][2][2][4];           // [d][rb][ks2][frag]
                #pragma unroll
                for (int d = 0; d < 2; d++)
                    #pragma unroll
                    for (int rb = 0; rb < 2; rb++)
                        #pragma unroll
                        for (int ks2 = 0; ks2 < 2; ks2++) {
                            const int kk = d * 256 + c4 + ksh * 32 + ks2 * 16 + q * 2;
                            float2 v00 = okA[rb] ? *(const float2*)(xb0 + (size_t)rA[rb] * 512 + kk)
                                                 : make_float2(0.f, 0.f);
                            float2 v10 = okB[rb] ? *(const float2*)(xb0 + (size_t)rB[rb] * 512 + kk)
                                                 : make_float2(0.f, 0.f);
                            float2 v01 = okA[rb] ? *(const float2*)(xb0 + (size_t)rA[rb] * 512 + kk + 8)
                                                 : make_float2(0.f, 0.f);
                            float2 v11 = okB[rb] ? *(const float2*)(xb0 + (size_t)rB[rb] * 512 + kk + 8)
                                                 : make_float2(0.f, 0.f);
                            xh[d][rb][ks2][0] = pkh(v00.x, v00.y);
                            xh[d][rb][ks2][1] = pkh(v10.x, v10.y);
                            xh[d][rb][ks2][2] = pkh(v01.x, v01.y);
                            xh[d][rb][ks2][3] = pkh(v11.x, v11.y);
                        }
                if (ch == 0 && ksh == 0) { CPA_WAIT0; __syncthreads(); }

                #pragma unroll
                for (int d = 0; d < 2; d++) {
                    const u32 wb = sb + OFF_UW + (u32)(d * 16896) + lmW
                                 + (u32)((c4 + ksh * 32) * 2);
                    u32 bh[4][4];
                    #pragma unroll
                    for (int nt = 0; nt < 4; nt++)
                        ldmx4(bh[nt][0], bh[nt][1], bh[nt][2], bh[nt][3], wb + (u32)(nt * 4224));
                    #pragma unroll
                    for (int nt = 0; nt < 4; nt++)
                        #pragma unroll
                        for (int rb = 0; rb < 2; rb++)
                            #pragma unroll
                            for (int ks2 = 0; ks2 < 2; ks2++)
                                mma16816(acc[d][rb][nt],
                                         xh[d][rb][ks2][0], xh[d][rb][ks2][1],
                                         xh[d][rb][ks2][2], xh[d][rb][ks2][3],
                                         bh[nt][ks2 * 2], bh[nt][ks2 * 2 + 1]);
                }
            }
        }

        // epilogue: +bias; d=0 -> P0 smem; d=1 -> pH/pL fragments
        float* P0f = (float*)(sm + OFF_P0);
        #pragma unroll
        for (int d = 0; d < 2; d++)
            #pragma unroll
            for (int rb = 0; rb < 2; rb++)
                #pragma unroll
                for (int nt = 0; nt < 4; nt++) {
                    int c0 = nt * 8 + q * 2;
                    float bx = *(float*)(sm + OFF_UB + (d * 32 + c0) * 4);
                    float by = *(float*)(sm + OFF_UB + (d * 32 + c0 + 1) * 4);
                    float px0 = acc[d][rb][nt].x + bx, py0 = acc[d][rb][nt].y + by;
                    float px1 = acc[d][rb][nt].z + bx, py1 = acc[d][rb][nt].w + by;
                    if (d == 0) {
                        P0f[rA[rb] * 36 + c0] = px0;  P0f[rA[rb] * 36 + c0 + 1] = py0;
                        P0f[rB[rb] * 36 + c0] = px1;  P0f[rB[rb] * 36 + c0 + 1] = py1;
                    } else {
                        int ks = nt >> 1, f0 = (nt & 1) * 2;
                        split2h(px0, py0, pH[rb][ks][f0],     pL[rb][ks][f0]);
                        split2h(px1, py1, pH[rb][ks][f0 + 1], pL[rb][ks][f0 + 1]);
                    }
                }
    }
    __syncthreads();   // phase-1 UW reads done; P0 visible

    // ================= Phase 2 =================
    float4 acc2[2][4];
    #pragma unroll
    for (int rb = 0; rb < 2; rb++)
        #pragma unroll
        for (int nt = 0; nt < 4; nt++) acc2[rb][nt] = make_float4(0.f, 0.f, 0.f, 0.f);
    {
        const float* P0f = (const float*)(sm + OFF_P0);

        #pragma unroll 1
        for (int i = tid; i < 1280; i += NTH)
            cpa16(sb + OFF_G + i * 16, g_GS + (size_t)i * 4);
        CPA_COMMIT;

        for (int cc = 0; cc < 4; cc++) {
            float4 svA[2][2], svB[2][2];
            #pragma unroll
            for (int rb = 0; rb < 2; rb++) {
                svA[rb][0] = *(const float4*)(P0f + rA[rb] * 36 + cc * 8);
                svA[rb][1] = *(const float4*)(P0f + rA[rb] * 36 + cc * 8 + 4);
                svB[rb][0] = *(const float4*)(P0f + rB[rb] * 36 + cc * 8);
                svB[rb][1] = *(const float4*)(P0f + rB[rb] * 36 + cc * 8 + 4);
            }
            CPA_WAIT0;
            __syncthreads();
            if (cc < 3) {
                int pp = (cc + 1) & 1;
                #pragma unroll 1
                for (int i = tid; i < 1280; i += NTH)
                    cpa16(sb + OFF_G + pp * 20480 + i * 16,
                          g_GS + (size_t)(cc + 1) * 5120 + (size_t)i * 4);
                CPA_COMMIT;
            } else {
                #pragma unroll 1
                for (int i = tid; i < 1280; i += NTH)
                    cpa16(sb + OFF_UO + i * 16, g_UOS + (size_t)i * 4);
                CPA_COMMIT;
            }
            const u32 gb = sb + OFF_G + (u32)((cc & 1) * 20480) + lm40;
            #pragma unroll
            for (int al = 0; al < 8; al++) {
                float s0[2], s1[2];
                #pragma unroll
                for (int rb = 0; rb < 2; rb++) {
                    s0[rb] = ((const float*)&svA[rb][al >> 2])[al & 3];
                    s1[rb] = ((const float*)&svB[rb][al >> 2])[al & 3];
                }
                u32 gh[4][4];
                #pragma unroll
                for (int nt = 0; nt < 4; nt++)
                    ldmx4(gh[nt][0], gh[nt][1], gh[nt][2], gh[nt][3],
                          gb + (u32)(al * 2560 + nt * 640));
                #pragma unroll
                for (int nt = 0; nt < 4; nt++) {
                    #pragma unroll
                    for (int rb = 0; rb < 2; rb++) {
                        float4 t4a = make_float4(0.f, 0.f, 0.f, 0.f);
                        float4 t4b = make_float4(0.f, 0.f, 0.f, 0.f);
                        mma16816(t4a, pH[rb][0][0], pH[rb][0][1], pH[rb][0][2], pH[rb][0][3], gh[nt][0], gh[nt][1]);
                        mma16816(t4b, pL[rb][0][0], pL[rb][0][1], pL[rb][0][2], pL[rb][0][3], gh[nt][0], gh[nt][1]);
                        mma16816(t4a, pH[rb][1][0], pH[rb][1][1], pH[rb][1][2], pH[rb][1][3], gh[nt][2], gh[nt][3]);
                        mma16816(t4b, pL[rb][1][0], pL[rb][1][1], pL[rb][1][2], pL[rb][1][3], gh[nt][2], gh[nt][3]);
                        acc2[rb][nt].x += s0[rb] * (t4a.x + t4b.x);
                        acc2[rb][nt].y += s0[rb] * (t4a.y + t4b.y);
                        acc2[rb][nt].z += s1[rb] * (t4a.z + t4b.z);
                        acc2[rb][nt].w += s1[rb] * (t4a.w + t4b.w);
                    }
                }
            }
        }
    }

    // ---- R epilogue: split directly into rH/rL fragments ----
    u32 rH[2][2][4], rL[2][2][4];
    #pragma unroll
    for (int rb = 0; rb < 2; rb++)
        #pragma unroll
        for (int nt = 0; nt < 4; nt++) {
            int ks = nt >> 1, f0 = (nt & 1) * 2;
            split2h(acc2[rb][nt].x, acc2[rb][nt].y, rH[rb][ks][f0],     rL[rb][ks][f0]);
            split2h(acc2[rb][nt].z, acc2[rb][nt].w, rH[rb][ks][f0 + 1], rL[rb][ks][f0 + 1]);
        }

    __syncthreads();
    #pragma unroll 1
    for (int i = tid; i < 1280; i += NTH)
        cpa16(sb + OFF_UO + 20480 + i * 16, g_UOS + 5120 + (size_t)i * 4);
    CPA_COMMIT;
    CPA_WAIT0;
    __syncthreads();

    // ================= Phase 3: Out = (Rhi+Rlo) @ (UoHi+UoLo)^T =================
    const u32 ub3 = sb + OFF_UO + lm40;
    #pragma unroll 2
    for (int np = 0; np < 16; np++) {
        u32 uh[2][4], ul[2][4];
        #pragma unroll
        for (int j = 0; j < 2; j++) {
            u32 ua = ub3 + (u32)((np * 2 + j) * 640);
            ldmx4(uh[j][0], uh[j][1], uh[j][2], uh[j][3], ua);
            ldmx4(ul[j][0], ul[j][1], ul[j][2], ul[j][3], ua + 20480);
        }
        #pragma unroll
        for (int j = 0; j < 2; j++) {
            const int o0 = (np * 2 + j) * 8 + q * 2;
            #pragma unroll
            for (int rb = 0; rb < 2; rb++) {
                float4 ta = make_float4(0.f, 0.f, 0.f, 0.f);
                float4 tb = make_float4(0.f, 0.f, 0.f, 0.f);
                mma16816(ta, rH[rb][0][0], rH[rb][0][1], rH[rb][0][2], rH[rb][0][3], uh[j][0], uh[j][1]);
                mma16816(tb, rL[rb][0][0], rL[rb][0][1], rL[rb][0][2], rL[rb][0][3], uh[j][0], uh[j][1]);
                mma16816(ta, rH[rb][1][0], rH[rb][1][1], rH[rb][1][2], rH[rb][1][3], uh[j][2], uh[j][3]);
                mma16816(tb, rL[rb][1][0], rL[rb][1][1], rL[rb][1][2], rL[rb][1][3], uh[j][2], uh[j][3]);
                mma16816(ta, rH[rb][0][0], rH[rb][0][1], rH[rb][0][2], rH[rb][0][3], ul[j][0], ul[j][1]);
                mma16816(ta, rH[rb][1][0], rH[rb][1][1], rH[rb][1][2], rH[rb][1][3], ul[j][2], ul[j][3]);
                if (okA[rb])
                    *(float2*)(out + (size_t)(base + rA[rb]) * 256 + o0)
                        = make_float2(ta.x + tb.x, ta.y + tb.y);
                if (okB[rb])
                    *(float2*)(out + (size_t)(base + rB[rb]) * 256 + o0)
                        = make_float2(ta.z + tb.z, ta.w + tb.w);
            }
        }
    }
}

extern "C" void kernel_launch(void* const* d_in, const int* in_sizes, int n_in,
                              void* d_out, int out_size)
{
    const float* X  = (const float*)d_in[0];
    const float* Gg = (const float*)d_in[1];
    const float* Uw = (const float*)d_in[2];
    const float* Ub = (const float*)d_in[3];
    const float* Uo = (const float*)d_in[4];
    float* outp = (float*)d_out;

    int nNodes = in_sizes[0] / 512;

    prep_kernel<<<32, 256>>>(Uw, Gg, Uo);

    cudaFuncSetAttribute(hosvd_mma,
                         cudaFuncAttributeMaxDynamicSharedMemorySize, SMEM_TOTAL);
    int grid = (nNodes + TN - 1) / TN;
    hosvd_mma<<<grid, NTH, SMEM_TOTAL>>>(X, Ub, outp, nNodes);
}